// round 1
// baseline (speedup 1.0000x reference)
#include <cuda_runtime.h>
#include <cuda_bf16.h>
#include <cstdint>

// MinimalThinkingRefiner: out = x + alpha*(x*scale + shift) where mask==2, else x.
// x: [B,S,H] fp32, mask: [B,S] int32, scale/shift: [H] fp32, alpha: scalar fp32 (device).
// HBM-bound streaming kernel: one CTA per row, float4 vectorized.

__global__ void __launch_bounds__(256, 8)
refiner_kernel(const float4* __restrict__ x,
               const int*    __restrict__ mask,
               const float4* __restrict__ scale,
               const float4* __restrict__ shift,
               const float*  __restrict__ alpha_p,
               float4* __restrict__ out,
               int hv /* H/4 */)
{
    const int row = blockIdx.x;
    const bool thinking = (mask[row] == 2);
    const size_t base = (size_t)row * hv;
    const float4* __restrict__ xr = x + base;
    float4* __restrict__ orow = out + base;

    if (!thinking) {
        // pure streaming copy
        #pragma unroll 4
        for (int i = threadIdx.x; i < hv; i += blockDim.x) {
            orow[i] = xr[i];
        }
    } else {
        const float a = *alpha_p;
        #pragma unroll 2
        for (int i = threadIdx.x; i < hv; i += blockDim.x) {
            float4 v = xr[i];
            float4 s = scale[i];
            float4 t = shift[i];
            // v + a*(v*s + t)  (fuses to 2 FFMA per lane-component)
            v.x = fmaf(a, fmaf(v.x, s.x, t.x), v.x);
            v.y = fmaf(a, fmaf(v.y, s.y, t.y), v.y);
            v.z = fmaf(a, fmaf(v.z, s.z, t.z), v.z);
            v.w = fmaf(a, fmaf(v.w, s.w, t.w), v.w);
            orow[i] = v;
        }
    }
}

extern "C" void kernel_launch(void* const* d_in, const int* in_sizes, int n_in,
                              void* d_out, int out_size)
{
    const float* x     = (const float*)d_in[0];   // [B,S,H]
    const int*   mask  = (const int*)d_in[1];     // [B,S]
    const float* scale = (const float*)d_in[2];   // [H]
    const float* shift = (const float*)d_in[3];   // [H]
    const float* alpha = (const float*)d_in[4];   // scalar

    const int rows = in_sizes[1];                 // B*S
    const int H    = in_sizes[0] / rows;          // hidden size (4096)
    const int hv   = H / 4;                       // float4 elements per row

    refiner_kernel<<<rows, 256>>>(
        (const float4*)x, mask, (const float4*)scale, (const float4*)shift,
        alpha, (float4*)d_out, hv);
}